// round 2
// baseline (speedup 1.0000x reference)
#include <cuda_runtime.h>

// Problem constants
#define NTOK 32768          // 32*1024 tokens
#define KC   1024           // codes
#define DD   256            // code dim
#define BM   16             // rows per CTA in main kernel
#define THR  512            // threads in main kernel (2 codes/thread)
#define TINV 10.0f          // 1/SOFTMAX_TEMP

// ---- output layout (flattened tuple order) ----
static const long OFF_ZQ    = 0;
static const long OFF_CODES = 8388608;
static const long OFF_LOSS  = 8421376;
static const long OFF_PERP  = 8421377;
static const long OFF_ENT   = 8421378;
static const long OFF_SOFT  = 8421379;
static const long OFF_NEMB  = 41975811;
static const long OFF_NCS   = 42237955;
static const long OFF_NEA   = 42238979;

// ---- device scratch ----
__device__ float g_e2[KC];
__device__ float g_counts[KC];
__device__ float g_esum[KC * DD];
__device__ float g_csn[KC];
__device__ float g_loss;

// packed 2xf32 fma (sm_10x): d = a*b + c elementwise on (lo,hi)
__device__ __forceinline__ unsigned long long fma2(unsigned long long a,
                                                   unsigned long long b,
                                                   unsigned long long c) {
    unsigned long long d;
    asm("fma.rn.f32x2 %0, %1, %2, %3;" : "=l"(d) : "l"(a), "l"(b), "l"(c));
    return d;
}
__device__ __forceinline__ float hsum2(unsigned long long v) {
    float2 f = *reinterpret_cast<float2*>(&v);
    return f.x + f.y;
}

// ---------------------------------------------------------------------------
__global__ void zero_k() {
    int i = blockIdx.x * 256 + threadIdx.x;
    if (i < KC * DD) g_esum[i] = 0.0f;
    if (i < KC)      g_counts[i] = 0.0f;
    if (i == 0)      g_loss = 0.0f;
}

// e2[k] = sum_d embed[k,d]^2
__global__ void e2_k(const float* __restrict__ embed) {
    int w    = (blockIdx.x * 256 + threadIdx.x) >> 5;
    int lane = threadIdx.x & 31;
    if (w >= KC) return;
    const float4* row = (const float4*)(embed + (size_t)w * DD);
    float s = 0.0f;
#pragma unroll
    for (int j = 0; j < 2; j++) {
        float4 v = row[lane + 32 * j];
        s += v.x * v.x + v.y * v.y + v.z * v.z + v.w * v.w;
    }
#pragma unroll
    for (int o = 16; o; o >>= 1) s += __shfl_xor_sync(0xffffffffu, s, o);
    if (lane == 0) g_e2[w] = s;
}

// ---------------------------------------------------------------------------
// Main kernel: BM=16 z-rows x all 1024 codes per CTA, 512 threads.
// Phase 1: f32x2-packed dot products. Each thread: 16 rows x 2 codes,
//          accumulators packed (even-d, odd-d) -> zero packing overhead.
// Phase 2: one warp per row: argmin, softmax, writes, EMA atomics.
extern __shared__ float smem[];

__global__ __launch_bounds__(THR, 1)
void vq_main(const float* __restrict__ z,
             const float* __restrict__ embed,
             float* __restrict__ out) {
    float* zs = smem;                 // [BM][DD]   16 KB
    float* sd = smem + BM * DD;       // [BM][KC]   64 KB

    int tid  = threadIdx.x;
    int row0 = blockIdx.x * BM;

    // load z tile (4096 floats = 1024 float4)
    {
        const float4* src = (const float4*)(z + (size_t)row0 * DD);
        float4*       dst = (float4*)zs;
#pragma unroll
        for (int i = 0; i < 2; i++) dst[tid + THR * i] = src[tid + THR * i];
    }
    __syncthreads();

    int c0 = tid * 2;
    const ulonglong2* ep0 = (const ulonglong2*)(embed + (size_t)(c0 + 0) * DD);
    const ulonglong2* ep1 = (const ulonglong2*)(embed + (size_t)(c0 + 1) * DD);
    const ulonglong2* zp  = (const ulonglong2*)zs;   // [BM][DD/4] of (2+2 floats)

    unsigned long long acc[BM][2];    // [row][code] packed (even-d, odd-d) sums
#pragma unroll
    for (int r = 0; r < BM; r++) { acc[r][0] = 0ull; acc[r][1] = 0ull; }

    ulonglong2 e0 = ep0[0], e1 = ep1[0];
#pragma unroll 1
    for (int j = 0; j < DD / 4; j++) {
        ulonglong2 n0, n1;
        if (j + 1 < DD / 4) { n0 = ep0[j + 1]; n1 = ep1[j + 1]; }
        else                { n0 = e0;         n1 = e1; }
#pragma unroll
        for (int r = 0; r < BM; r++) {
            ulonglong2 zv = zp[r * (DD / 4) + j];    // warp-broadcast LDS.128
            acc[r][0] = fma2(zv.x, e0.x, acc[r][0]);
            acc[r][0] = fma2(zv.y, e0.y, acc[r][0]);
            acc[r][1] = fma2(zv.x, e1.x, acc[r][1]);
            acc[r][1] = fma2(zv.y, e1.y, acc[r][1]);
        }
        e0 = n0; e1 = n1;
    }

    // dist surrogate s = e2 - 2*dot  (||z||^2 cancels in argmin & softmax)
    float q0 = g_e2[c0], q1 = g_e2[c0 + 1];
#pragma unroll
    for (int r = 0; r < BM; r++) {
        float2 s;
        s.x = q0 - 2.0f * hsum2(acc[r][0]);
        s.y = q1 - 2.0f * hsum2(acc[r][1]);
        *((float2*)(sd + r * KC + c0)) = s;
    }
    __syncthreads();

    // ---- per-row reduction: one warp per row (16 warps, 16 rows) ----
    int lane = tid & 31, r = tid >> 5;
    {
        int grow = row0 + r;
        float* row = sd + r * KC;

        // min / argmin (tie-break: smallest index, matching jnp.argmin)
        float mn = 3.4e38f; int arg = 0;
#pragma unroll
        for (int j = 0; j < 32; j++) {
            float v = row[j * 32 + lane];
            if (v < mn) { mn = v; arg = j * 32 + lane; }
        }
#pragma unroll
        for (int o = 16; o; o >>= 1) {
            float ov = __shfl_xor_sync(0xffffffffu, mn, o);
            int   oa = __shfl_xor_sync(0xffffffffu, arg, o);
            if (ov < mn || (ov == mn && oa < arg)) { mn = ov; arg = oa; }
        }

        // exp + sum (stable: shift by row-min dist)
        float sum = 0.0f;
#pragma unroll
        for (int j = 0; j < 32; j++) {
            float v = __expf((mn - row[j * 32 + lane]) * TINV);
            row[j * 32 + lane] = v;
            sum += v;
        }
#pragma unroll
        for (int o = 16; o; o >>= 1) sum += __shfl_xor_sync(0xffffffffu, sum, o);
        float inv = 1.0f / sum;

        float* soft = out + OFF_SOFT + (long)grow * KC;
#pragma unroll
        for (int j = 0; j < 32; j++)
            soft[j * 32 + lane] = row[j * 32 + lane] * inv;

        // z_q (= z_q_st numerically), commitment-loss partial, EMA sums
        int code = arg;
        const float* er = embed + (size_t)code * DD;
        float* zq = out + OFF_ZQ + (long)grow * DD;
        float lp = 0.0f;
#pragma unroll
        for (int j = 0; j < 8; j++) {
            int d    = j * 32 + lane;
            float ev = er[d];
            float zv = zs[r * DD + d];
            zq[d] = ev;
            float df = zv - ev;
            lp += df * df;
            atomicAdd(&g_esum[code * DD + d], zv);
        }
#pragma unroll
        for (int o = 16; o; o >>= 1) lp += __shfl_xor_sync(0xffffffffu, lp, o);
        if (lane == 0) {
            out[OFF_CODES + grow] = (float)code;
            atomicAdd(&g_counts[code], 1.0f);
            atomicAdd(&g_loss, lp);
        }
    }
}

// ---------------------------------------------------------------------------
// fin1 (grid=1): EMA cluster_size, normalizer, entropy/perplexity, loss mean.
__global__ void fin1(const float* __restrict__ cs, float* __restrict__ out) {
    __shared__ float red[1024];
    int k = threadIdx.x;

    float cnt = g_counts[k];
    float ncs = 0.99f * cs[k] + 0.01f * cnt;
    out[OFF_NCS + k] = ncs;

    red[k] = ncs;
    __syncthreads();
    for (int s = 512; s; s >>= 1) { if (k < s) red[k] += red[k + s]; __syncthreads(); }
    float n = red[0];
    __syncthreads();

    g_csn[k] = (ncs + 1e-5f) / (n + 1024.0f * 1e-5f) * n;

    float p = cnt * (1.0f / 32768.0f);
    red[k] = -p * logf(p + 1e-10f);
    __syncthreads();
    for (int s = 512; s; s >>= 1) { if (k < s) red[k] += red[k + s]; __syncthreads(); }

    if (k == 0) {
        float ent = red[0];
        out[OFF_ENT]  = ent;
        out[OFF_PERP] = expf(ent);
        out[OFF_LOSS] = g_loss * (1.0f / (32768.0f * 256.0f));
    }
}

// fin2 (grid-wide): new_embed_avg + new_embed over 262144 elements.
__global__ void fin2(const float* __restrict__ ea, float* __restrict__ out) {
    int idx = blockIdx.x * 256 + threadIdx.x;
    float v = 0.99f * ea[idx] + 0.01f * g_esum[idx];
    out[OFF_NEA  + idx] = v;
    out[OFF_NEMB + idx] = v / g_csn[idx >> 8];
}

// ---------------------------------------------------------------------------
extern "C" void kernel_launch(void* const* d_in, const int* in_sizes, int n_in,
                              void* d_out, int out_size) {
    const float* z     = (const float*)d_in[0];
    const float* embed = (const float*)d_in[1];
    const float* cs    = (const float*)d_in[2];
    const float* ea    = (const float*)d_in[3];
    float* out = (float*)d_out;

    const int smem_bytes = (BM * DD + BM * KC) * 4;   // 81920
    cudaFuncSetAttribute(vq_main, cudaFuncAttributeMaxDynamicSharedMemorySize,
                         smem_bytes);

    zero_k<<<1024, 256>>>();
    e2_k<<<128, 256>>>(embed);
    vq_main<<<NTOK / BM, THR, smem_bytes>>>(z, embed, out);
    fin1<<<1, 1024>>>(cs, out);
    fin2<<<1024, 256>>>(ea, out);
}

// round 4
// speedup vs baseline: 2.3411x; 2.3411x over previous
#include <cuda_runtime.h>
#include <cuda_fp16.h>
#include <cstdint>

// Problem constants
#define NTOK 32768
#define KC   1024
#define DD   256
#define KSPL 768            // split-f16 contraction length (3*256)
#define TINV 10.0f

// Output layout (flattened tuple order)
static const long OFF_ZQ    = 0;
static const long OFF_CODES = 8388608;
static const long OFF_LOSS  = 8421376;
static const long OFF_PERP  = 8421377;
static const long OFF_ENT   = 8421378;
static const long OFF_SOFT  = 8421379;   // NOTE: only 4B-aligned -> scalar access only
static const long OFF_NEMB  = 41975811;
static const long OFF_NCS   = 42237955;
static const long OFF_NEA   = 42238979;

// Device scratch
__device__ float  g_e2[KC];
__device__ float  g_counts[KC];
__device__ float  g_esum[KC * DD];
__device__ float  g_csn[KC];
__device__ float  g_loss;
__device__ __half g_A[(size_t)NTOK * KSPL];   // [z_hi | z_lo | z_hi]
__device__ __half g_B[(size_t)KC   * KSPL];   // [e_hi | e_hi | e_lo]

// ---------------------------------------------------------------------------
__device__ __forceinline__ uint32_t smem_u32(const void* p) {
    uint32_t a;
    asm("{ .reg .u64 t; cvta.to.shared.u64 t, %1; cvt.u32.u64 %0, t; }"
        : "=r"(a) : "l"(p));
    return a;
}
#define SWZ(off) ((off) ^ (((off) >> 3) & 0x70))

__device__ __forceinline__ void cp16(uint32_t s, const void* g) {
    asm volatile("cp.async.cg.shared.global [%0], [%1], 16;"
                 :: "r"(s), "l"(g) : "memory");
}

#define LDSM4(r, addr) \
    asm volatile("ldmatrix.sync.aligned.m8n8.x4.shared.b16 {%0,%1,%2,%3}, [%4];" \
        : "=r"((r)[0]), "=r"((r)[1]), "=r"((r)[2]), "=r"((r)[3]) : "r"(addr))

#define MMA16816(c, a, b) \
    asm volatile("mma.sync.aligned.m16n8k16.row.col.f32.f16.f16.f32 " \
        "{%0,%1,%2,%3}, {%4,%5,%6,%7}, {%8,%9}, {%0,%1,%2,%3};" \
        : "+f"((c)[0]), "+f"((c)[1]), "+f"((c)[2]), "+f"((c)[3]) \
        : "r"((a)[0]), "r"((a)[1]), "r"((a)[2]), "r"((a)[3]), \
          "r"((b)[0]), "r"((b)[1]))

// ---------------------------------------------------------------------------
__global__ void zero_k() {
    int i = blockIdx.x * 256 + threadIdx.x;
    if (i < KC * DD) g_esum[i] = 0.0f;
    if (i < KC)      g_counts[i] = 0.0f;
    if (i == 0)      g_loss = 0.0f;
}

__global__ void e2_k(const float* __restrict__ embed) {
    int w    = (blockIdx.x * 256 + threadIdx.x) >> 5;
    int lane = threadIdx.x & 31;
    if (w >= KC) return;
    const float4* row = (const float4*)(embed + (size_t)w * DD);
    float s = 0.0f;
#pragma unroll
    for (int j = 0; j < 2; j++) {
        float4 v = row[lane + 32 * j];
        s += v.x * v.x + v.y * v.y + v.z * v.z + v.w * v.w;
    }
#pragma unroll
    for (int o = 16; o; o >>= 1) s += __shfl_xor_sync(0xffffffffu, s, o);
    if (lane == 0) g_e2[w] = s;
}

// split f32 -> (hi, lo) f16; A' = [hi | lo | hi]
__global__ void conv_z(const float* __restrict__ z) {
    int idx = blockIdx.x * 256 + threadIdx.x;      // float4 index
    int n = idx >> 6, d4 = (idx & 63) * 4;
    float4 v = ((const float4*)z)[idx];
    __half hx = __float2half(v.x), hy = __float2half(v.y);
    __half hz = __float2half(v.z), hw = __float2half(v.w);
    __half lx = __float2half(v.x - __half2float(hx));
    __half ly = __float2half(v.y - __half2float(hy));
    __half lz = __float2half(v.z - __half2float(hz));
    __half lw = __float2half(v.w - __half2float(hw));
    __half* r = g_A + (size_t)n * KSPL;
    __half2 h0 = __halves2half2(hx, hy), h1 = __halves2half2(hz, hw);
    __half2 l0 = __halves2half2(lx, ly), l1 = __halves2half2(lz, lw);
    *(__half2*)(r + d4)           = h0; *(__half2*)(r + d4 + 2)       = h1;
    *(__half2*)(r + 256 + d4)     = l0; *(__half2*)(r + 256 + d4 + 2) = l1;
    *(__half2*)(r + 512 + d4)     = h0; *(__half2*)(r + 512 + d4 + 2) = h1;
}

// B' = [hi | hi | lo]
__global__ void conv_e(const float* __restrict__ embed) {
    int idx = blockIdx.x * 256 + threadIdx.x;
    int n = idx >> 6, d4 = (idx & 63) * 4;
    float4 v = ((const float4*)embed)[idx];
    __half hx = __float2half(v.x), hy = __float2half(v.y);
    __half hz = __float2half(v.z), hw = __float2half(v.w);
    __half lx = __float2half(v.x - __half2float(hx));
    __half ly = __float2half(v.y - __half2float(hy));
    __half lz = __float2half(v.z - __half2float(hz));
    __half lw = __float2half(v.w - __half2float(hw));
    __half* r = g_B + (size_t)n * KSPL;
    __half2 h0 = __halves2half2(hx, hy), h1 = __halves2half2(hz, hw);
    __half2 l0 = __halves2half2(lx, ly), l1 = __halves2half2(lz, lw);
    *(__half2*)(r + d4)           = h0; *(__half2*)(r + d4 + 2)       = h1;
    *(__half2*)(r + 256 + d4)     = h0; *(__half2*)(r + 256 + d4 + 2) = h1;
    *(__half2*)(r + 512 + d4)     = l0; *(__half2*)(r + 512 + d4 + 2) = l1;
}

// ---------------------------------------------------------------------------
// HMMA GEMM: CTA = 128 tokens x 128 codes, K=768 in 12 chunks of 64 f16.
// 8 warps as 4(m) x 2(n); each warp 32x64. Double-buffered cp.async.
#define SM_BUF 32768     // per stage: A 16KB + B 16KB
#define SM_TOT 65536
#define NCH    12

__device__ __forceinline__ void load_chunk(uint32_t sb, const char* Ag,
                                           const char* Bg, int c, int buf,
                                           int tid) {
    uint32_t base = sb + buf * SM_BUF;
#pragma unroll
    for (int q = 0; q < 4; q++) {
        int i = tid + 256 * q, r = i >> 3, j = i & 7;
        uint32_t off = (uint32_t)(r * 128 + j * 16);
        cp16(base + SWZ(off), Ag + (size_t)r * (KSPL * 2) + c * 128 + j * 16);
    }
#pragma unroll
    for (int q = 0; q < 4; q++) {
        int i = tid + 256 * q, r = i >> 3, j = i & 7;
        uint32_t off = (uint32_t)(r * 128 + j * 16);
        cp16(base + 16384 + SWZ(off), Bg + (size_t)r * (KSPL * 2) + c * 128 + j * 16);
    }
    asm volatile("cp.async.commit_group;" ::: "memory");
}

extern __shared__ char gsm[];

__global__ __launch_bounds__(256, 1)
void vq_gemm(float* __restrict__ out) {
    uint32_t sb = smem_u32(gsm);
    int tid = threadIdx.x, lane = tid & 31, wid = tid >> 5;
    int row0 = blockIdx.x * 128, col0 = blockIdx.y * 128;
    int wm = (wid & 3) * 32, wn = (wid >> 2) * 64;

    const char* Ag = (const char*)g_A + (size_t)row0 * (KSPL * 2);
    const char* Bg = (const char*)g_B + (size_t)col0 * (KSPL * 2);

    float acc[2][8][4] = {};

    load_chunk(sb, Ag, Bg, 0, 0, tid);

    for (int c = 0; c < NCH; c++) {
        if (c + 1 < NCH) {
            load_chunk(sb, Ag, Bg, c + 1, (c + 1) & 1, tid);
            asm volatile("cp.async.wait_group 1;" ::: "memory");
        } else {
            asm volatile("cp.async.wait_group 0;" ::: "memory");
        }
        __syncthreads();

        uint32_t sa = sb + (c & 1) * SM_BUF;
        uint32_t sB = sa + 16384;
#pragma unroll
        for (int ks = 0; ks < 4; ks++) {
            uint32_t a[2][4];
#pragma unroll
            for (int mt = 0; mt < 2; mt++) {
                uint32_t off = (uint32_t)((wm + mt * 16 + (lane & 15)) * 128
                                          + ks * 32 + (lane >> 4) * 16);
                LDSM4(a[mt], sa + SWZ(off));
            }
            uint32_t b[8][2];
#pragma unroll
            for (int p = 0; p < 4; p++) {
                uint32_t r4[4];
                uint32_t off = (uint32_t)((wn + p * 16 + (lane & 7)
                                           + ((lane >> 4) << 3)) * 128
                                          + ks * 32 + ((lane >> 3) & 1) * 16);
                LDSM4(r4, sB + SWZ(off));
                b[2 * p][0] = r4[0];     b[2 * p][1] = r4[1];
                b[2 * p + 1][0] = r4[2]; b[2 * p + 1][1] = r4[3];
            }
#pragma unroll
            for (int mt = 0; mt < 2; mt++)
#pragma unroll
                for (int nt = 0; nt < 8; nt++)
                    MMA16816(acc[mt][nt], a[mt], b[nt]);
        }
        __syncthreads();
    }

    // Epilogue: scalar stores (soft region only 4B-aligned).
    // C fragment: c0,c1 -> (row g, col q*2 / +1); c2,c3 -> row g+8.
#pragma unroll
    for (int mt = 0; mt < 2; mt++) {
#pragma unroll
        for (int nt = 0; nt < 8; nt++) {
            int r = row0 + wm + mt * 16 + (lane >> 2);
            int cc = col0 + wn + nt * 8 + (lane & 3) * 2;
            float* d0 = out + OFF_SOFT + (size_t)r * KC + cc;
            d0[0]        = acc[mt][nt][0];
            d0[1]        = acc[mt][nt][1];
            d0[8 * KC]   = acc[mt][nt][2];
            d0[8 * KC + 1] = acc[mt][nt][3];
        }
    }
}

// ---------------------------------------------------------------------------
// Per-row epilogue: dist = e2 - 2*dot, argmin, softmax, z_q, loss, EMA.
// One warp per row; all soft-region accesses scalar (coalesced across lanes).
__global__ __launch_bounds__(256)
void vq_epi(const float* __restrict__ z,
            const float* __restrict__ embed,
            float* __restrict__ out) {
    __shared__ float e2s[KC];
    int tid = threadIdx.x, lane = tid & 31, w = tid >> 5;
#pragma unroll
    for (int i = 0; i < 4; i++) e2s[tid + 256 * i] = g_e2[tid + 256 * i];
    __syncthreads();

    int row = blockIdx.x * 8 + w;
    float* dot = out + OFF_SOFT + (size_t)row * KC;

    float dv[32];
    float mn = 3.4e38f; int arg = 0;
#pragma unroll
    for (int j = 0; j < 32; j++) {
        int k = j * 32 + lane;
        float d = e2s[k] - 2.0f * dot[k];
        dv[j] = d;
        if (d < mn) { mn = d; arg = k; }
    }
#pragma unroll
    for (int o = 16; o; o >>= 1) {
        float ov = __shfl_xor_sync(0xffffffffu, mn, o);
        int   oa = __shfl_xor_sync(0xffffffffu, arg, o);
        if (ov < mn || (ov == mn && oa < arg)) { mn = ov; arg = oa; }
    }

    float sum = 0.0f;
#pragma unroll
    for (int j = 0; j < 32; j++) {
        float v = __expf((mn - dv[j]) * TINV);
        dv[j] = v;
        sum += v;
    }
#pragma unroll
    for (int o = 16; o; o >>= 1) sum += __shfl_xor_sync(0xffffffffu, sum, o);
    float inv = 1.0f / sum;
#pragma unroll
    for (int j = 0; j < 32; j++)
        dot[j * 32 + lane] = dv[j] * inv;

    // z_q, loss, EMA
    int code = arg;
    const float* er = embed + (size_t)code * DD;
    const float* zr = z     + (size_t)row  * DD;
    float* zq = out + OFF_ZQ + (size_t)row * DD;
    float lp = 0.0f;
#pragma unroll
    for (int j = 0; j < 8; j++) {
        int d = j * 32 + lane;
        float ev = er[d], zv = zr[d];
        zq[d] = ev;
        float df = zv - ev;
        lp += df * df;
        atomicAdd(&g_esum[code * DD + d], zv);
    }
#pragma unroll
    for (int o = 16; o; o >>= 1) lp += __shfl_xor_sync(0xffffffffu, lp, o);
    if (lane == 0) {
        out[OFF_CODES + row] = (float)code;
        atomicAdd(&g_counts[code], 1.0f);
        atomicAdd(&g_loss, lp);
    }
}

// ---------------------------------------------------------------------------
__global__ void fin1(const float* __restrict__ cs, float* __restrict__ out) {
    __shared__ float red[1024];
    int k = threadIdx.x;
    float cnt = g_counts[k];
    float ncs = 0.99f * cs[k] + 0.01f * cnt;
    out[OFF_NCS + k] = ncs;
    red[k] = ncs;
    __syncthreads();
    for (int s = 512; s; s >>= 1) { if (k < s) red[k] += red[k + s]; __syncthreads(); }
    float n = red[0];
    __syncthreads();
    g_csn[k] = (ncs + 1e-5f) / (n + 1024.0f * 1e-5f) * n;
    float p = cnt * (1.0f / 32768.0f);
    red[k] = -p * logf(p + 1e-10f);
    __syncthreads();
    for (int s = 512; s; s >>= 1) { if (k < s) red[k] += red[k + s]; __syncthreads(); }
    if (k == 0) {
        float ent = red[0];
        out[OFF_ENT]  = ent;
        out[OFF_PERP] = expf(ent);
        out[OFF_LOSS] = g_loss * (1.0f / (32768.0f * 256.0f));
    }
}

__global__ void fin2(const float* __restrict__ ea, float* __restrict__ out) {
    int idx = blockIdx.x * 256 + threadIdx.x;
    float v = 0.99f * ea[idx] + 0.01f * g_esum[idx];
    out[OFF_NEA  + idx] = v;
    out[OFF_NEMB + idx] = v / g_csn[idx >> 8];
}

// ---------------------------------------------------------------------------
extern "C" void kernel_launch(void* const* d_in, const int* in_sizes, int n_in,
                              void* d_out, int out_size) {
    const float* z     = (const float*)d_in[0];
    const float* embed = (const float*)d_in[1];
    const float* cs    = (const float*)d_in[2];
    const float* ea    = (const float*)d_in[3];
    float* out = (float*)d_out;

    cudaFuncSetAttribute(vq_gemm, cudaFuncAttributeMaxDynamicSharedMemorySize,
                         SM_TOT);

    zero_k<<<1024, 256>>>();
    conv_z<<<8192, 256>>>(z);
    conv_e<<<256, 256>>>(embed);
    e2_k<<<128, 256>>>(embed);
    vq_gemm<<<dim3(256, 8), 256, SM_TOT>>>(out);
    vq_epi<<<4096, 256>>>(z, embed, out);
    fin1<<<1, 1024>>>(cs, out);
    fin2<<<1024, 256>>>(ea, out);
}

// round 5
// speedup vs baseline: 2.8656x; 1.2240x over previous
#include <cuda_runtime.h>
#include <cuda_fp16.h>
#include <cstdint>

// Problem constants
#define NTOK 32768
#define KC   1024
#define DD   256
#define KSPL 768            // split-f16 contraction length (3*256)
#define TINV 10.0f

// Output layout (flattened tuple order)
static const long OFF_ZQ    = 0;
static const long OFF_CODES = 8388608;
static const long OFF_LOSS  = 8421376;
static const long OFF_PERP  = 8421377;
static const long OFF_ENT   = 8421378;
static const long OFF_SOFT  = 8421379;   // only 4B-aligned -> scalar access only
static const long OFF_NEMB  = 41975811;
static const long OFF_NCS   = 42237955;
static const long OFF_NEA   = 42238979;

// Device scratch
__device__ float  g_e2[KC];
__device__ float  g_counts[KC];
__device__ float  g_esum[KC * DD];
__device__ float  g_csn[KC];
__device__ float  g_loss;
__device__ __half g_A[(size_t)NTOK * KSPL];   // [z_hi | z_lo | z_hi]
__device__ __half g_B[(size_t)KC   * KSPL];   // [e_hi | e_hi | e_lo]

// ---------------------------------------------------------------------------
__device__ __forceinline__ uint32_t smem_u32(const void* p) {
    uint32_t a;
    asm("{ .reg .u64 t; cvta.to.shared.u64 t, %1; cvt.u32.u64 %0, t; }"
        : "=r"(a) : "l"(p));
    return a;
}
#define SWZ(off) ((off) ^ (((off) >> 3) & 0x70))

__device__ __forceinline__ void cp16(uint32_t s, const void* g) {
    asm volatile("cp.async.cg.shared.global [%0], [%1], 16;"
                 :: "r"(s), "l"(g) : "memory");
}

#define LDSM4(r, addr) \
    asm volatile("ldmatrix.sync.aligned.m8n8.x4.shared.b16 {%0,%1,%2,%3}, [%4];" \
        : "=r"((r)[0]), "=r"((r)[1]), "=r"((r)[2]), "=r"((r)[3]) : "r"(addr))

#define MMA16816(c, a, b) \
    asm volatile("mma.sync.aligned.m16n8k16.row.col.f32.f16.f16.f32 " \
        "{%0,%1,%2,%3}, {%4,%5,%6,%7}, {%8,%9}, {%0,%1,%2,%3};" \
        : "+f"((c)[0]), "+f"((c)[1]), "+f"((c)[2]), "+f"((c)[3]) \
        : "r"((a)[0]), "r"((a)[1]), "r"((a)[2]), "r"((a)[3]), \
          "r"((b)[0]), "r"((b)[1]))

// ---------------------------------------------------------------------------
// e2[k] = ||embed_k||^2, fused with scratch zeroing (one launch).
__global__ void e2z_k(const float* __restrict__ embed) {
    int t = blockIdx.x * 256 + threadIdx.x;     // 32768 threads
#pragma unroll
    for (int j = 0; j < 8; j++) g_esum[t * 8 + j] = 0.0f;
    if (t < KC) g_counts[t] = 0.0f;
    if (t == 0) g_loss = 0.0f;

    int w = t >> 5, lane = t & 31;
    const float4* row = (const float4*)(embed + (size_t)w * DD);
    float s = 0.0f;
#pragma unroll
    for (int j = 0; j < 2; j++) {
        float4 v = row[lane + 32 * j];
        s += v.x * v.x + v.y * v.y + v.z * v.z + v.w * v.w;
    }
#pragma unroll
    for (int o = 16; o; o >>= 1) s += __shfl_xor_sync(0xffffffffu, s, o);
    if (lane == 0) g_e2[w] = s;
}

// split f32 -> (hi, lo) f16; A' = [hi | lo | hi]
__global__ void conv_z(const float* __restrict__ z) {
    int idx = blockIdx.x * 256 + threadIdx.x;
    int n = idx >> 6, d4 = (idx & 63) * 4;
    float4 v = ((const float4*)z)[idx];
    __half hx = __float2half(v.x), hy = __float2half(v.y);
    __half hz = __float2half(v.z), hw = __float2half(v.w);
    __half lx = __float2half(v.x - __half2float(hx));
    __half ly = __float2half(v.y - __half2float(hy));
    __half lz = __float2half(v.z - __half2float(hz));
    __half lw = __float2half(v.w - __half2float(hw));
    __half* r = g_A + (size_t)n * KSPL;
    __half2 h0 = __halves2half2(hx, hy), h1 = __halves2half2(hz, hw);
    __half2 l0 = __halves2half2(lx, ly), l1 = __halves2half2(lz, lw);
    *(__half2*)(r + d4)           = h0; *(__half2*)(r + d4 + 2)       = h1;
    *(__half2*)(r + 256 + d4)     = l0; *(__half2*)(r + 256 + d4 + 2) = l1;
    *(__half2*)(r + 512 + d4)     = h0; *(__half2*)(r + 512 + d4 + 2) = h1;
}

// B' = [hi | hi | lo]
__global__ void conv_e(const float* __restrict__ embed) {
    int idx = blockIdx.x * 256 + threadIdx.x;
    int n = idx >> 6, d4 = (idx & 63) * 4;
    float4 v = ((const float4*)embed)[idx];
    __half hx = __float2half(v.x), hy = __float2half(v.y);
    __half hz = __float2half(v.z), hw = __float2half(v.w);
    __half lx = __float2half(v.x - __half2float(hx));
    __half ly = __float2half(v.y - __half2float(hy));
    __half lz = __float2half(v.z - __half2float(hz));
    __half lw = __float2half(v.w - __half2float(hw));
    __half* r = g_B + (size_t)n * KSPL;
    __half2 h0 = __halves2half2(hx, hy), h1 = __halves2half2(hz, hw);
    __half2 l0 = __halves2half2(lx, ly), l1 = __halves2half2(lz, lw);
    *(__half2*)(r + d4)           = h0; *(__half2*)(r + d4 + 2)       = h1;
    *(__half2*)(r + 256 + d4)     = h0; *(__half2*)(r + 256 + d4 + 2) = h1;
    *(__half2*)(r + 512 + d4)     = l0; *(__half2*)(r + 512 + d4 + 2) = l1;
}

// ---------------------------------------------------------------------------
// HMMA GEMM: CTA = 128 tokens x 128 codes, K=768 in 12 chunks of 64 f16.
// 8 warps as 4(m) x 2(n), warp tile 32x64. 3-stage cp.async pipeline.
// Writes dist = e2 - 2*dot into the soft region (scratch).
#define SM_STG 32768     // per stage: A 16KB + B 16KB
#define SM_TOT (3 * SM_STG)
#define NCH    12

__device__ __forceinline__ void load_chunk(uint32_t sb, const char* Ag,
                                           const char* Bg, int c, int stg,
                                           int tid) {
    uint32_t base = sb + stg * SM_STG;
#pragma unroll
    for (int q = 0; q < 4; q++) {
        int i = tid + 256 * q, r = i >> 3, j = i & 7;
        uint32_t off = (uint32_t)(r * 128 + j * 16);
        cp16(base + SWZ(off), Ag + (size_t)r * (KSPL * 2) + c * 128 + j * 16);
    }
#pragma unroll
    for (int q = 0; q < 4; q++) {
        int i = tid + 256 * q, r = i >> 3, j = i & 7;
        uint32_t off = (uint32_t)(r * 128 + j * 16);
        cp16(base + 16384 + SWZ(off), Bg + (size_t)r * (KSPL * 2) + c * 128 + j * 16);
    }
    asm volatile("cp.async.commit_group;" ::: "memory");
}

extern __shared__ char gsm[];

__global__ __launch_bounds__(256, 2)
void vq_gemm(float* __restrict__ out) {
    __shared__ float e2t[128];
    uint32_t sb = smem_u32(gsm);
    int tid = threadIdx.x, lane = tid & 31, wid = tid >> 5;
    int row0 = blockIdx.x * 128, col0 = blockIdx.y * 128;
    int wm = (wid & 3) * 32, wn = (wid >> 2) * 64;

    if (tid < 128) e2t[tid] = g_e2[col0 + tid];

    const char* Ag = (const char*)g_A + (size_t)row0 * (KSPL * 2);
    const char* Bg = (const char*)g_B + (size_t)col0 * (KSPL * 2);

    float acc[2][8][4] = {};

    load_chunk(sb, Ag, Bg, 0, 0, tid);
    load_chunk(sb, Ag, Bg, 1, 1, tid);

    int stg = 0, lstg = 2;
    for (int c = 0; c < NCH; c++) {
        if (c < NCH - 1) asm volatile("cp.async.wait_group 1;" ::: "memory");
        else             asm volatile("cp.async.wait_group 0;" ::: "memory");
        __syncthreads();
        if (c + 2 < NCH) load_chunk(sb, Ag, Bg, c + 2, lstg, tid);

        uint32_t sa = sb + stg * SM_STG;
        uint32_t sB = sa + 16384;
#pragma unroll
        for (int ks = 0; ks < 4; ks++) {
            uint32_t a[2][4];
#pragma unroll
            for (int mt = 0; mt < 2; mt++) {
                uint32_t off = (uint32_t)((wm + mt * 16 + (lane & 15)) * 128
                                          + ks * 32 + (lane >> 4) * 16);
                LDSM4(a[mt], sa + SWZ(off));
            }
            uint32_t b[8][2];
#pragma unroll
            for (int p = 0; p < 4; p++) {
                uint32_t r4[4];
                uint32_t off = (uint32_t)((wn + p * 16 + (lane & 7)
                                           + ((lane >> 4) << 3)) * 128
                                          + ks * 32 + ((lane >> 3) & 1) * 16);
                LDSM4(r4, sB + SWZ(off));
                b[2 * p][0] = r4[0];     b[2 * p][1] = r4[1];
                b[2 * p + 1][0] = r4[2]; b[2 * p + 1][1] = r4[3];
            }
#pragma unroll
            for (int mt = 0; mt < 2; mt++)
#pragma unroll
                for (int nt = 0; nt < 8; nt++)
                    MMA16816(acc[mt][nt], a[mt], b[nt]);
        }
        stg  = (stg  == 2) ? 0 : stg + 1;
        lstg = (lstg == 2) ? 0 : lstg + 1;
    }

    // Epilogue: dist = e2 - 2*dot, scalar stores (region only 4B-aligned).
#pragma unroll
    for (int mt = 0; mt < 2; mt++) {
#pragma unroll
        for (int nt = 0; nt < 8; nt++) {
            int r  = row0 + wm + mt * 16 + (lane >> 2);
            int lc = wn + nt * 8 + (lane & 3) * 2;
            float* d0 = out + OFF_SOFT + (size_t)r * KC + col0 + lc;
            d0[0]          = e2t[lc]     - 2.0f * acc[mt][nt][0];
            d0[1]          = e2t[lc + 1] - 2.0f * acc[mt][nt][1];
            d0[8 * KC]     = e2t[lc]     - 2.0f * acc[mt][nt][2];
            d0[8 * KC + 1] = e2t[lc + 1] - 2.0f * acc[mt][nt][3];
        }
    }
}

// ---------------------------------------------------------------------------
// Per-row epilogue: argmin, softmax (in-place over dist), z_q, loss, EMA.
__global__ __launch_bounds__(256)
void vq_epi(const float* __restrict__ z,
            const float* __restrict__ embed,
            float* __restrict__ out) {
    int tid = threadIdx.x, lane = tid & 31, w = tid >> 5;
    int row = blockIdx.x * 8 + w;
    float* dist = out + OFF_SOFT + (size_t)row * KC;

    float dv[32];
    float mn = 3.4e38f; int arg = 0;
#pragma unroll
    for (int j = 0; j < 32; j++) {
        int k = j * 32 + lane;
        float d = dist[k];
        dv[j] = d;
        if (d < mn) { mn = d; arg = k; }
    }
#pragma unroll
    for (int o = 16; o; o >>= 1) {
        float ov = __shfl_xor_sync(0xffffffffu, mn, o);
        int   oa = __shfl_xor_sync(0xffffffffu, arg, o);
        if (ov < mn || (ov == mn && oa < arg)) { mn = ov; arg = oa; }
    }

    float sum = 0.0f;
#pragma unroll
    for (int j = 0; j < 32; j++) {
        float v = __expf((mn - dv[j]) * TINV);
        dv[j] = v;
        sum += v;
    }
#pragma unroll
    for (int o = 16; o; o >>= 1) sum += __shfl_xor_sync(0xffffffffu, sum, o);
    float inv = 1.0f / sum;
#pragma unroll
    for (int j = 0; j < 32; j++)
        dist[j * 32 + lane] = dv[j] * inv;

    // z_q, loss, EMA
    int code = arg;
    const float* er = embed + (size_t)code * DD;
    const float* zr = z     + (size_t)row  * DD;
    float* zq = out + OFF_ZQ + (size_t)row * DD;
    float lp = 0.0f;
#pragma unroll
    for (int j = 0; j < 8; j++) {
        int d = j * 32 + lane;
        float ev = er[d], zv = zr[d];
        zq[d] = ev;
        float df = zv - ev;
        lp += df * df;
        atomicAdd(&g_esum[code * DD + d], zv);
    }
#pragma unroll
    for (int o = 16; o; o >>= 1) lp += __shfl_xor_sync(0xffffffffu, lp, o);
    if (lane == 0) {
        out[OFF_CODES + row] = (float)code;
        atomicAdd(&g_counts[code], 1.0f);
        atomicAdd(&g_loss, lp);
    }
}

// ---------------------------------------------------------------------------
__global__ void fin1(const float* __restrict__ cs, float* __restrict__ out) {
    __shared__ float red[1024];
    int k = threadIdx.x;
    float cnt = g_counts[k];
    float ncs = 0.99f * cs[k] + 0.01f * cnt;
    out[OFF_NCS + k] = ncs;
    red[k] = ncs;
    __syncthreads();
    for (int s = 512; s; s >>= 1) { if (k < s) red[k] += red[k + s]; __syncthreads(); }
    float n = red[0];
    __syncthreads();
    g_csn[k] = (ncs + 1e-5f) / (n + 1024.0f * 1e-5f) * n;
    float p = cnt * (1.0f / 32768.0f);
    red[k] = -p * logf(p + 1e-10f);
    __syncthreads();
    for (int s = 512; s; s >>= 1) { if (k < s) red[k] += red[k + s]; __syncthreads(); }
    if (k == 0) {
        float ent = red[0];
        out[OFF_ENT]  = ent;
        out[OFF_PERP] = expf(ent);
        out[OFF_LOSS] = g_loss * (1.0f / (32768.0f * 256.0f));
    }
}

__global__ void fin2(const float* __restrict__ ea, float* __restrict__ out) {
    int idx = blockIdx.x * 256 + threadIdx.x;
    float v = 0.99f * ea[idx] + 0.01f * g_esum[idx];
    out[OFF_NEA  + idx] = v;
    out[OFF_NEMB + idx] = v / g_csn[idx >> 8];
}

// ---------------------------------------------------------------------------
extern "C" void kernel_launch(void* const* d_in, const int* in_sizes, int n_in,
                              void* d_out, int out_size) {
    const float* z     = (const float*)d_in[0];
    const float* embed = (const float*)d_in[1];
    const float* cs    = (const float*)d_in[2];
    const float* ea    = (const float*)d_in[3];
    float* out = (float*)d_out;

    cudaFuncSetAttribute(vq_gemm, cudaFuncAttributeMaxDynamicSharedMemorySize,
                         SM_TOT);

    e2z_k<<<128, 256>>>(embed);
    conv_z<<<8192, 256>>>(z);
    conv_e<<<256, 256>>>(embed);
    vq_gemm<<<dim3(256, 8), 256, SM_TOT>>>(out);
    vq_epi<<<4096, 256>>>(z, embed, out);
    fin1<<<1, 1024>>>(cs, out);
    fin2<<<1024, 256>>>(ea, out);
}